// round 3
// baseline (speedup 1.0000x reference)
#include <cuda_runtime.h>
#include <math.h>

#define T_SEQ  4096
#define D_MODEL 1024
#define NH      16
#define CH      64

// ---------------- scratch (device globals; no allocation allowed) ----------
__device__ uint2 g_Q2[NH * T_SEQ * CH];    // [h][t][c] tf32 {hi,lo}, rope applied
__device__ uint2 g_K2[NH * T_SEQ * CH];
__device__ uint2 g_V2[NH * T_SEQ * CH];
__device__ float g_att[T_SEQ * D_MODEL];   // [t][h*64+c]
__device__ float g_sin[T_SEQ * 32];
__device__ float g_cos[T_SEQ * 32];

// ---------------- RoPE sin/cos table ---------------------------------------
__global__ void rope_table_kernel() {
    int t = blockIdx.x;
    int p = threadIdx.x;
    double inv = pow(10000.0, -(double)(2 * p) / 64.0);
    float ang = (float)t * (float)inv;
    float s, c;
    sincosf(ang, &s, &c);
    g_sin[t * 32 + p] = s;
    g_cos[t * 32 + p] = c;
}

// ---------------- tf32 helpers ----------------------------------------------
__device__ __forceinline__ unsigned f2tf32(float x) {
    unsigned r;
    asm("cvt.rna.tf32.f32 %0, %1;" : "=r"(r) : "f"(x));
    return r;
}

__device__ __forceinline__ uint2 split1(float x) {
    unsigned h = f2tf32(x);
    unsigned l = f2tf32(x - __uint_as_float(h));
    return make_uint2(h, l);
}

__device__ __forceinline__ void mma_tf32(float* d, const unsigned* a, const unsigned* b) {
    asm volatile(
        "mma.sync.aligned.m16n8k8.row.col.f32.tf32.tf32.f32 "
        "{%0,%1,%2,%3},{%4,%5,%6,%7},{%8,%9},{%0,%1,%2,%3};"
        : "+f"(d[0]), "+f"(d[1]), "+f"(d[2]), "+f"(d[3])
        : "r"(a[0]), "r"(a[1]), "r"(a[2]), "r"(a[3]), "r"(b[0]), "r"(b[1]));
}

__device__ __forceinline__ void split4(float4 v, unsigned* hp, unsigned* lp) {
    unsigned h0 = f2tf32(v.x), h1 = f2tf32(v.y), h2 = f2tf32(v.z), h3 = f2tf32(v.w);
    *(uint4*)hp = make_uint4(h0, h1, h2, h3);
    unsigned l0 = f2tf32(v.x - __uint_as_float(h0));
    unsigned l1 = f2tf32(v.y - __uint_as_float(h1));
    unsigned l2 = f2tf32(v.z - __uint_as_float(h2));
    unsigned l3 = f2tf32(v.w - __uint_as_float(h3));
    *(uint4*)lp = make_uint4(l0, l1, l2, l3);
}

// ---------------- tf32 GEMM: C = A(row) * B(row as N x K)^T -----------------
// EPI=0: qkv (+rope, split, scatter into g_Q2/g_K2/g_V2), EPI=1: proj -> out
#define SK 20

template<int EPI>
__global__ __launch_bounds__(256) void gemm_tf32(
    const float* __restrict__ Ain, const float* __restrict__ B,
    float* __restrict__ out) {
    __shared__ unsigned Ah[128][SK], Al[128][SK], Bh[128][SK], Bl[128][SK];

    const float* A = (EPI == 1) ? g_att : Ain;

    int tid  = threadIdx.x;
    int lane = tid & 31;
    int warp = tid >> 5;
    int bm = blockIdx.y, bn = blockIdx.x;
    int warp_m = (warp >> 2) * 64;
    int warp_n = (warp & 3) * 32;
    int g  = lane >> 2;
    int tc = lane & 3;

    int r  = tid >> 2;
    int k4 = (tid & 3) * 4;
    const float* Ap0 = A + (size_t)(bm * 128 + r)      * D_MODEL + k4;
    const float* Ap1 = A + (size_t)(bm * 128 + r + 64) * D_MODEL + k4;
    const float* Bp0 = B + (size_t)(bn * 128 + r)      * D_MODEL + k4;
    const float* Bp1 = B + (size_t)(bn * 128 + r + 64) * D_MODEL + k4;

    float acc[4][4][4];
#pragma unroll
    for (int mt = 0; mt < 4; mt++)
#pragma unroll
        for (int nt = 0; nt < 4; nt++)
#pragma unroll
            for (int i = 0; i < 4; i++) acc[mt][nt][i] = 0.f;

    float4 sa0 = *(const float4*)(Ap0);
    float4 sa1 = *(const float4*)(Ap1);
    float4 sb0 = *(const float4*)(Bp0);
    float4 sb1 = *(const float4*)(Bp1);

    for (int k0 = 0; k0 < D_MODEL; k0 += 16) {
        __syncthreads();
        split4(sa0, &Ah[r][k4],      &Al[r][k4]);
        split4(sa1, &Ah[r + 64][k4], &Al[r + 64][k4]);
        split4(sb0, &Bh[r][k4],      &Bl[r][k4]);
        split4(sb1, &Bh[r + 64][k4], &Bl[r + 64][k4]);
        __syncthreads();
        if (k0 + 16 < D_MODEL) {
            sa0 = *(const float4*)(Ap0 + k0 + 16);
            sa1 = *(const float4*)(Ap1 + k0 + 16);
            sb0 = *(const float4*)(Bp0 + k0 + 16);
            sb1 = *(const float4*)(Bp1 + k0 + 16);
        }
#pragma unroll
        for (int kk = 0; kk < 16; kk += 8) {
            unsigned afh[4][4], afl[4][4], bfh[4][2], bfl[4][2];
#pragma unroll
            for (int mt = 0; mt < 4; mt++) {
                int row = warp_m + mt * 16 + g;
                afh[mt][0] = Ah[row][kk + tc];
                afh[mt][1] = Ah[row + 8][kk + tc];
                afh[mt][2] = Ah[row][kk + tc + 4];
                afh[mt][3] = Ah[row + 8][kk + tc + 4];
                afl[mt][0] = Al[row][kk + tc];
                afl[mt][1] = Al[row + 8][kk + tc];
                afl[mt][2] = Al[row][kk + tc + 4];
                afl[mt][3] = Al[row + 8][kk + tc + 4];
            }
#pragma unroll
            for (int nt = 0; nt < 4; nt++) {
                int col = warp_n + nt * 8 + g;
                bfh[nt][0] = Bh[col][kk + tc];
                bfh[nt][1] = Bh[col][kk + tc + 4];
                bfl[nt][0] = Bl[col][kk + tc];
                bfl[nt][1] = Bl[col][kk + tc + 4];
            }
#pragma unroll
            for (int mt = 0; mt < 4; mt++)
#pragma unroll
                for (int nt = 0; nt < 4; nt++) {
                    mma_tf32(acc[mt][nt], afh[mt], bfh[nt]);
                    mma_tf32(acc[mt][nt], afh[mt], bfl[nt]);
                    mma_tf32(acc[mt][nt], afl[mt], bfh[nt]);
                }
        }
    }

    // ---- epilogue ----
    if (EPI == 0) {
        int mat = (bn * 128) >> 10;                 // 0=q,1=k,2=v
        uint2* dst = (mat == 0) ? g_Q2 : (mat == 1 ? g_K2 : g_V2);
#pragma unroll
        for (int mt = 0; mt < 4; mt++)
#pragma unroll
            for (int nt = 0; nt < 4; nt++) {
                int colb = bn * 128 + warp_n + nt * 8 + 2 * tc;
                int cm = colb & 1023;
                int h = cm >> 6, cc = cm & 63, p = cc >> 1;
#pragma unroll
                for (int half = 0; half < 2; half++) {
                    int row = bm * 128 + warp_m + mt * 16 + g + half * 8;
                    float e = acc[mt][nt][half * 2 + 0];
                    float o = acc[mt][nt][half * 2 + 1];
                    if (mat != 2) {
                        float sn = g_sin[row * 32 + p];
                        float cs = g_cos[row * 32 + p];
                        float e2 = e * cs - o * sn;
                        o = o * cs + e * sn;
                        e = e2;
                    }
                    size_t idx = ((size_t)h * T_SEQ + row) * CH + cc;
                    uint2 es = split1(e), os = split1(o);
                    *(uint4*)&dst[idx] = make_uint4(es.x, es.y, os.x, os.y);
                }
            }
    } else {
#pragma unroll
        for (int mt = 0; mt < 4; mt++)
#pragma unroll
            for (int nt = 0; nt < 4; nt++) {
                int colb = bn * 128 + warp_n + nt * 8 + 2 * tc;
#pragma unroll
                for (int half = 0; half < 2; half++) {
                    int row = bm * 128 + warp_m + mt * 16 + g + half * 8;
                    *(float2*)&out[(size_t)row * D_MODEL + colb] =
                        make_float2(acc[mt][nt][half * 2 + 0],
                                    acc[mt][nt][half * 2 + 1]);
                }
            }
    }
}

// ---------------- tensor-core flash attention -------------------------------
// smem tiles: uint2 {tf32 hi, lo}, row-stride 68 elements (conflict-free LDS.64)
#define FS 68
#define OFF_Q  0
#define OFF_K  (64 * FS)
#define OFF_V  (2 * 64 * FS)
#define OFF_P  (3 * 64 * FS)
#define OFF_RED (4 * 64 * FS)                 // float[2][64] max + float[2][64] sum
#define FLASH_SMEM ((4 * 64 * FS + 128) * 8)

__global__ __launch_bounds__(256) void flash_mma() {
    extern __shared__ uint2 sm2[];
    uint2* QT = sm2 + OFF_Q;     // [r][c]
    uint2* KT = sm2 + OFF_K;     // [s][c]
    uint2* VT = sm2 + OFF_V;     // [c][s]  (V transposed)
    uint2* PT = sm2 + OFF_P;     // [r][s]
    float* wmaxs = (float*)(sm2 + OFF_RED);   // [2][64]
    float* wsums = wmaxs + 128;               // [2][64]

    int h  = blockIdx.y;
    int qi = 63 - blockIdx.x;                 // heavy tiles first
    int tid = threadIdx.x;
    int lane = tid & 31;
    int warp = tid >> 5;
    int g  = lane >> 2;
    int tc = lane & 3;
    int warp_m = (warp >> 1) * 16;
    int warp_n = (warp & 1) * 32;
    int wn = warp & 1;

    size_t hbase = (size_t)h * T_SEQ * CH;

    // load Q tile (uint4 = 2 uint2 elements)
    for (int i = tid; i < 64 * 32; i += 256) {
        int r = i >> 5, c2 = (i & 31) * 2;
        uint4 q = *(const uint4*)&g_Q2[hbase + (size_t)(qi * 64 + r) * CH + c2];
        *(uint4*)&QT[r * FS + c2] = q;
    }

    int ar0 = (warp_m + g) * FS;
    int ar1 = ar0 + 8 * FS;

    float m0 = -1e30f, m1 = -1e30f, l0 = 0.f, l1 = 0.f;
    float o[4][4];
#pragma unroll
    for (int nt = 0; nt < 4; nt++)
#pragma unroll
        for (int i = 0; i < 4; i++) o[nt][i] = 0.f;

    for (int kt = 0; kt <= qi; kt++) {
        __syncthreads();   // prev PV reads done (covers Q load on iter 0)
        for (int i = tid; i < 64 * 32; i += 256) {
            int r = i >> 5, c2 = (i & 31) * 2;
            size_t gi = hbase + (size_t)(kt * 64 + r) * CH + c2;
            uint4 kk4 = *(const uint4*)&g_K2[gi];
            *(uint4*)&KT[r * FS + c2] = kk4;
            uint4 vv4 = *(const uint4*)&g_V2[gi];
            VT[(c2)     * FS + r] = make_uint2(vv4.x, vv4.y);
            VT[(c2 + 1) * FS + r] = make_uint2(vv4.z, vv4.w);
        }
        __syncthreads();

        // ---- S = Q K^T (3-term tf32) ----
        float sacc[4][4];
#pragma unroll
        for (int nt = 0; nt < 4; nt++)
#pragma unroll
            for (int i = 0; i < 4; i++) sacc[nt][i] = 0.f;

#pragma unroll
        for (int kk = 0; kk < 64; kk += 8) {
            uint2 qa0 = QT[ar0 + kk + tc];
            uint2 qa1 = QT[ar1 + kk + tc];
            uint2 qa2 = QT[ar0 + kk + tc + 4];
            uint2 qa3 = QT[ar1 + kk + tc + 4];
            unsigned ah[4] = {qa0.x, qa1.x, qa2.x, qa3.x};
            unsigned al[4] = {qa0.y, qa1.y, qa2.y, qa3.y};
#pragma unroll
            for (int nt = 0; nt < 4; nt++) {
                int col = (warp_n + nt * 8 + g) * FS;
                uint2 kb0 = KT[col + kk + tc];
                uint2 kb1 = KT[col + kk + tc + 4];
                unsigned bh[2] = {kb0.x, kb1.x};
                unsigned bl[2] = {kb0.y, kb1.y};
                mma_tf32(sacc[nt], ah, bh);
                mma_tf32(sacc[nt], al, bh);
                mma_tf32(sacc[nt], ah, bl);
            }
        }

        // scale + causal mask
        bool diag = (kt == qi);
        int r0l = warp_m + g, r1l = r0l + 8;
#pragma unroll
        for (int nt = 0; nt < 4; nt++) {
            int c0 = warp_n + nt * 8 + 2 * tc;
#pragma unroll
            for (int i = 0; i < 4; i++) {
                float v = sacc[nt][i] * 0.125f;
                int col = c0 + (i & 1);
                int row = (i < 2) ? r0l : r1l;
                if (diag && col > row) v = -1e30f;
                sacc[nt][i] = v;
            }
        }

        // ---- online softmax ----
        float lm0 = -1e30f, lm1 = -1e30f;
#pragma unroll
        for (int nt = 0; nt < 4; nt++) {
            lm0 = fmaxf(lm0, fmaxf(sacc[nt][0], sacc[nt][1]));
            lm1 = fmaxf(lm1, fmaxf(sacc[nt][2], sacc[nt][3]));
        }
        lm0 = fmaxf(lm0, __shfl_xor_sync(0xffffffffu, lm0, 1));
        lm0 = fmaxf(lm0, __shfl_xor_sync(0xffffffffu, lm0, 2));
        lm1 = fmaxf(lm1, __shfl_xor_sync(0xffffffffu, lm1, 1));
        lm1 = fmaxf(lm1, __shfl_xor_sync(0xffffffffu, lm1, 2));
        if (tc == 0) {
            wmaxs[wn * 64 + r0l] = lm0;
            wmaxs[wn * 64 + r1l] = lm1;
        }
        __syncthreads();

        float gm0 = fmaxf(wmaxs[r0l], wmaxs[64 + r0l]);
        float gm1 = fmaxf(wmaxs[r1l], wmaxs[64 + r1l]);
        float mn0 = fmaxf(m0, gm0);
        float mn1 = fmaxf(m1, gm1);
        float a0 = __expf(m0 - mn0);
        float a1 = __expf(m1 - mn1);
        float ps0 = 0.f, ps1 = 0.f;
#pragma unroll
        for (int nt = 0; nt < 4; nt++) {
            float p0 = __expf(sacc[nt][0] - mn0);
            float p1 = __expf(sacc[nt][1] - mn0);
            float p2 = __expf(sacc[nt][2] - mn1);
            float p3 = __expf(sacc[nt][3] - mn1);
            ps0 += p0 + p1;
            ps1 += p2 + p3;
            int c0 = warp_n + nt * 8 + 2 * tc;
            uint2 s0 = split1(p0), s1 = split1(p1), s2 = split1(p2), s3 = split1(p3);
            *(uint4*)&PT[r0l * FS + c0] = make_uint4(s0.x, s0.y, s1.x, s1.y);
            *(uint4*)&PT[r1l * FS + c0] = make_uint4(s2.x, s2.y, s3.x, s3.y);
        }
        ps0 += __shfl_xor_sync(0xffffffffu, ps0, 1);
        ps0 += __shfl_xor_sync(0xffffffffu, ps0, 2);
        ps1 += __shfl_xor_sync(0xffffffffu, ps1, 1);
        ps1 += __shfl_xor_sync(0xffffffffu, ps1, 2);
        if (tc == 0) {
            wsums[wn * 64 + r0l] = ps0;
            wsums[wn * 64 + r1l] = ps1;
        }
        m0 = mn0; m1 = mn1;
        __syncthreads();

        l0 = l0 * a0 + wsums[r0l] + wsums[64 + r0l];
        l1 = l1 * a1 + wsums[r1l] + wsums[64 + r1l];
#pragma unroll
        for (int nt = 0; nt < 4; nt++) {
            o[nt][0] *= a0; o[nt][1] *= a0;
            o[nt][2] *= a1; o[nt][3] *= a1;
        }

        // ---- O += P V (3-term tf32) ----
#pragma unroll
        for (int kk = 0; kk < 64; kk += 8) {
            uint2 pa0 = PT[ar0 + kk + tc];
            uint2 pa1 = PT[ar1 + kk + tc];
            uint2 pa2 = PT[ar0 + kk + tc + 4];
            uint2 pa3 = PT[ar1 + kk + tc + 4];
            unsigned ah[4] = {pa0.x, pa1.x, pa2.x, pa3.x};
            unsigned al[4] = {pa0.y, pa1.y, pa2.y, pa3.y};
#pragma unroll
            for (int nt = 0; nt < 4; nt++) {
                int col = (warp_n + nt * 8 + g) * FS;
                uint2 vb0 = VT[col + kk + tc];
                uint2 vb1 = VT[col + kk + tc + 4];
                unsigned bh[2] = {vb0.x, vb1.x};
                unsigned bl[2] = {vb0.y, vb1.y};
                mma_tf32(o[nt], ah, bh);
                mma_tf32(o[nt], al, bh);
                mma_tf32(o[nt], ah, bl);
            }
        }
    }

    // write normalized output
    float il0 = 1.0f / l0;
    float il1 = 1.0f / l1;
    int t0 = qi * 64 + warp_m + g;
#pragma unroll
    for (int nt = 0; nt < 4; nt++) {
        int c0 = h * CH + warp_n + nt * 8 + 2 * tc;
        *(float2*)&g_att[(size_t)t0 * D_MODEL + c0] =
            make_float2(o[nt][0] * il0, o[nt][1] * il0);
        *(float2*)&g_att[(size_t)(t0 + 8) * D_MODEL + c0] =
            make_float2(o[nt][2] * il1, o[nt][3] * il1);
    }
}

// ---------------- launch -----------------------------------------------------
extern "C" void kernel_launch(void* const* d_in, const int* in_sizes, int n_in,
                              void* d_out, int out_size) {
    const float* x     = (const float*)d_in[0];
    const float* Wqkv  = (const float*)d_in[1];
    const float* Wproj = (const float*)d_in[2];
    float* out = (float*)d_out;

    cudaFuncSetAttribute(flash_mma,
                         cudaFuncAttributeMaxDynamicSharedMemorySize, FLASH_SMEM);

    rope_table_kernel<<<T_SEQ, 32>>>();
    gemm_tf32<0><<<dim3(3 * D_MODEL / 128, T_SEQ / 128), 256>>>(x, Wqkv, nullptr);
    flash_mma<<<dim3(64, NH), 256, FLASH_SMEM>>>();
    gemm_tf32<1><<<dim3(D_MODEL / 128, T_SEQ / 128), 256>>>(nullptr, Wproj, out);
}

// round 4
// speedup vs baseline: 1.2647x; 1.2647x over previous
#include <cuda_runtime.h>
#include <math.h>

#define T_SEQ  4096
#define D_MODEL 1024
#define NH      16
#define CH      64

// ---------------- scratch (device globals; no allocation allowed) ----------
__device__ uint2 g_Q2[NH * T_SEQ * CH];    // [h][t][c] tf32 {hi,lo}, rope applied
__device__ uint2 g_K2[NH * T_SEQ * CH];
__device__ uint2 g_V2[NH * T_SEQ * CH];
__device__ float g_att[T_SEQ * D_MODEL];   // [t][h*64+c]
__device__ float g_sin[T_SEQ * 32];
__device__ float g_cos[T_SEQ * 32];

// ---------------- RoPE sin/cos table ---------------------------------------
__global__ void rope_table_kernel() {
    int t = blockIdx.x;
    int p = threadIdx.x;
    double inv = pow(10000.0, -(double)(2 * p) / 64.0);
    float ang = (float)t * (float)inv;
    float s, c;
    sincosf(ang, &s, &c);
    g_sin[t * 32 + p] = s;
    g_cos[t * 32 + p] = c;
}

// ---------------- tf32 helpers ----------------------------------------------
__device__ __forceinline__ unsigned f2tf32(float x) {
    unsigned r;
    asm("cvt.rna.tf32.f32 %0, %1;" : "=r"(r) : "f"(x));
    return r;
}

__device__ __forceinline__ uint2 split1(float x) {
    unsigned h = f2tf32(x);
    unsigned l = f2tf32(x - __uint_as_float(h));
    return make_uint2(h, l);
}

__device__ __forceinline__ void mma_tf32(float* d, const unsigned* a, const unsigned* b) {
    asm volatile(
        "mma.sync.aligned.m16n8k8.row.col.f32.tf32.tf32.f32 "
        "{%0,%1,%2,%3},{%4,%5,%6,%7},{%8,%9},{%0,%1,%2,%3};"
        : "+f"(d[0]), "+f"(d[1]), "+f"(d[2]), "+f"(d[3])
        : "r"(a[0]), "r"(a[1]), "r"(a[2]), "r"(a[3]), "r"(b[0]), "r"(b[1]));
}

__device__ __forceinline__ void split4(float4 v, unsigned* hp, unsigned* lp) {
    unsigned h0 = f2tf32(v.x), h1 = f2tf32(v.y), h2 = f2tf32(v.z), h3 = f2tf32(v.w);
    *(uint4*)hp = make_uint4(h0, h1, h2, h3);
    unsigned l0 = f2tf32(v.x - __uint_as_float(h0));
    unsigned l1 = f2tf32(v.y - __uint_as_float(h1));
    unsigned l2 = f2tf32(v.z - __uint_as_float(h2));
    unsigned l3 = f2tf32(v.w - __uint_as_float(h3));
    *(uint4*)lp = make_uint4(l0, l1, l2, l3);
}

// fast exp2 on the fma pipe (arg <= 0), rel err ~2e-6
__device__ __forceinline__ float exp2_fast(float y) {
    y = fmaxf(y, -125.f);
    float n = rintf(y);
    float f = y - n;                 // [-0.5, 0.5]
    float p = 1.3333558e-3f;
    p = fmaf(p, f, 9.6181291e-3f);
    p = fmaf(p, f, 5.5504109e-2f);
    p = fmaf(p, f, 2.4022651e-1f);
    p = fmaf(p, f, 6.9314718e-1f);
    p = fmaf(p, f, 1.0f);
    return p * __int_as_float(((int)n + 127) << 23);
}

// ---------------- tf32 GEMM: C = A(row) * B(row as N x K)^T -----------------
// EPI=0: qkv (+rope, split, scatter into g_Q2/g_K2/g_V2), EPI=1: proj -> out
#define SK 20

template<int EPI>
__global__ __launch_bounds__(256) void gemm_tf32(
    const float* __restrict__ Ain, const float* __restrict__ B,
    float* __restrict__ out) {
    __shared__ unsigned Ah[128][SK], Al[128][SK], Bh[128][SK], Bl[128][SK];

    const float* A = (EPI == 1) ? g_att : Ain;

    int tid  = threadIdx.x;
    int lane = tid & 31;
    int warp = tid >> 5;
    int bm = blockIdx.y, bn = blockIdx.x;
    int warp_m = (warp >> 2) * 64;
    int warp_n = (warp & 3) * 32;
    int g  = lane >> 2;
    int tc = lane & 3;

    int r  = tid >> 2;
    int k4 = (tid & 3) * 4;
    const float* Ap0 = A + (size_t)(bm * 128 + r)      * D_MODEL + k4;
    const float* Ap1 = A + (size_t)(bm * 128 + r + 64) * D_MODEL + k4;
    const float* Bp0 = B + (size_t)(bn * 128 + r)      * D_MODEL + k4;
    const float* Bp1 = B + (size_t)(bn * 128 + r + 64) * D_MODEL + k4;

    float acc[4][4][4];
#pragma unroll
    for (int mt = 0; mt < 4; mt++)
#pragma unroll
        for (int nt = 0; nt < 4; nt++)
#pragma unroll
            for (int i = 0; i < 4; i++) acc[mt][nt][i] = 0.f;

    float4 sa0 = *(const float4*)(Ap0);
    float4 sa1 = *(const float4*)(Ap1);
    float4 sb0 = *(const float4*)(Bp0);
    float4 sb1 = *(const float4*)(Bp1);

    for (int k0 = 0; k0 < D_MODEL; k0 += 16) {
        __syncthreads();
        split4(sa0, &Ah[r][k4],      &Al[r][k4]);
        split4(sa1, &Ah[r + 64][k4], &Al[r + 64][k4]);
        split4(sb0, &Bh[r][k4],      &Bl[r][k4]);
        split4(sb1, &Bh[r + 64][k4], &Bl[r + 64][k4]);
        __syncthreads();
        if (k0 + 16 < D_MODEL) {
            sa0 = *(const float4*)(Ap0 + k0 + 16);
            sa1 = *(const float4*)(Ap1 + k0 + 16);
            sb0 = *(const float4*)(Bp0 + k0 + 16);
            sb1 = *(const float4*)(Bp1 + k0 + 16);
        }
#pragma unroll
        for (int kk = 0; kk < 16; kk += 8) {
            unsigned afh[4][4], afl[4][4], bfh[4][2], bfl[4][2];
#pragma unroll
            for (int mt = 0; mt < 4; mt++) {
                int row = warp_m + mt * 16 + g;
                afh[mt][0] = Ah[row][kk + tc];
                afh[mt][1] = Ah[row + 8][kk + tc];
                afh[mt][2] = Ah[row][kk + tc + 4];
                afh[mt][3] = Ah[row + 8][kk + tc + 4];
                afl[mt][0] = Al[row][kk + tc];
                afl[mt][1] = Al[row + 8][kk + tc];
                afl[mt][2] = Al[row][kk + tc + 4];
                afl[mt][3] = Al[row + 8][kk + tc + 4];
            }
#pragma unroll
            for (int nt = 0; nt < 4; nt++) {
                int col = warp_n + nt * 8 + g;
                bfh[nt][0] = Bh[col][kk + tc];
                bfh[nt][1] = Bh[col][kk + tc + 4];
                bfl[nt][0] = Bl[col][kk + tc];
                bfl[nt][1] = Bl[col][kk + tc + 4];
            }
#pragma unroll
            for (int mt = 0; mt < 4; mt++)
#pragma unroll
                for (int nt = 0; nt < 4; nt++) {
                    mma_tf32(acc[mt][nt], afh[mt], bfh[nt]);
                    mma_tf32(acc[mt][nt], afh[mt], bfl[nt]);
                    mma_tf32(acc[mt][nt], afl[mt], bfh[nt]);
                }
        }
    }

    // ---- epilogue ----
    if (EPI == 0) {
        int mat = (bn * 128) >> 10;                 // 0=q,1=k,2=v
        uint2* dst = (mat == 0) ? g_Q2 : (mat == 1 ? g_K2 : g_V2);
#pragma unroll
        for (int mt = 0; mt < 4; mt++)
#pragma unroll
            for (int nt = 0; nt < 4; nt++) {
                int colb = bn * 128 + warp_n + nt * 8 + 2 * tc;
                int cm = colb & 1023;
                int h = cm >> 6, cc = cm & 63, p = cc >> 1;
#pragma unroll
                for (int half = 0; half < 2; half++) {
                    int row = bm * 128 + warp_m + mt * 16 + g + half * 8;
                    float e = acc[mt][nt][half * 2 + 0];
                    float o = acc[mt][nt][half * 2 + 1];
                    if (mat != 2) {
                        float sn = g_sin[row * 32 + p];
                        float cs = g_cos[row * 32 + p];
                        float e2 = e * cs - o * sn;
                        o = o * cs + e * sn;
                        e = e2;
                    }
                    size_t idx = ((size_t)h * T_SEQ + row) * CH + cc;
                    uint2 es = split1(e), os = split1(o);
                    *(uint4*)&dst[idx] = make_uint4(es.x, es.y, os.x, os.y);
                }
            }
    } else {
#pragma unroll
        for (int mt = 0; mt < 4; mt++)
#pragma unroll
            for (int nt = 0; nt < 4; nt++) {
                int colb = bn * 128 + warp_n + nt * 8 + 2 * tc;
#pragma unroll
                for (int half = 0; half < 2; half++) {
                    int row = bm * 128 + warp_m + mt * 16 + g + half * 8;
                    *(float2*)&out[(size_t)row * D_MODEL + colb] =
                        make_float2(acc[mt][nt][half * 2 + 0],
                                    acc[mt][nt][half * 2 + 1]);
                }
            }
    }
}

// ---------------- tensor-core flash attention v2 -----------------------------
// BM=128 x BN=64; 8 warps, each owns 16 full rows (no cross-warp softmax).
// smem float arrays: Q/K/P stride 68 (conflict-free A/B frag LDS), V stride 72.
#define QH_OFF 0
#define QL_OFF 8704
#define KH_OFF 17408
#define KL_OFF 21760
#define VH_OFF 26112
#define VL_OFF 30720
#define PH_OFF 35328
#define PL_OFF 44032
#define FLASH_SMEM (52736 * 4)

__global__ __launch_bounds__(256) void flash_mma2() {
    extern __shared__ float sf[];
    float* Qh = sf + QH_OFF;  float* Ql = sf + QL_OFF;
    float* Kh = sf + KH_OFF;  float* Kl = sf + KL_OFF;
    float* Vh = sf + VH_OFF;  float* Vl = sf + VL_OFF;
    float* Ph = sf + PH_OFF;  float* Pl = sf + PL_OFF;

    int h  = blockIdx.y;
    int qi = 31 - blockIdx.x;                 // heavy tiles first
    int tid = threadIdx.x;
    int lane = tid & 31;
    int warp = tid >> 5;
    int g  = lane >> 2;
    int tc = lane & 3;
    int wm = warp * 16;

    size_t hbase = (size_t)h * T_SEQ * CH;

    // load Q tile: 128 rows x 64 cols of {hi,lo}
#pragma unroll
    for (int t = 0; t < 16; t++) {
        int i = tid + t * 256;
        int r = i >> 5, c2 = (i & 31) * 2;
        uint4 q = *(const uint4*)&g_Q2[hbase + (size_t)(qi * 128 + r) * CH + c2];
        *(float2*)&Qh[r * 68 + c2] =
            make_float2(__uint_as_float(q.x), __uint_as_float(q.z));
        *(float2*)&Ql[r * 68 + c2] =
            make_float2(__uint_as_float(q.y), __uint_as_float(q.w));
    }

    float m0 = -1e30f, m1 = -1e30f, l0 = 0.f, l1 = 0.f;
    float o[8][4];
#pragma unroll
    for (int nt = 0; nt < 8; nt++)
#pragma unroll
        for (int i = 0; i < 4; i++) o[nt][i] = 0.f;

    const float SC = 0.125f * 1.44269504f;     // scale * log2(e)
    int row0 = qi * 128 + wm + g;
    int row1 = row0 + 8;
    int ktmax = 2 * qi + 1;

    for (int kt = 0; kt <= ktmax; kt++) {
        __syncthreads();   // all warps done reading prev K/V
#pragma unroll
        for (int t = 0; t < 8; t++) {
            int i = tid + t * 256;
            int r = i >> 5, c2 = (i & 31) * 2;
            size_t gi = hbase + (size_t)(kt * 64 + r) * CH + c2;
            uint4 kk4 = *(const uint4*)&g_K2[gi];
            *(float2*)&Kh[r * 68 + c2] =
                make_float2(__uint_as_float(kk4.x), __uint_as_float(kk4.z));
            *(float2*)&Kl[r * 68 + c2] =
                make_float2(__uint_as_float(kk4.y), __uint_as_float(kk4.w));
            uint4 vv4 = *(const uint4*)&g_V2[gi];
            *(float2*)&Vh[r * 72 + c2] =
                make_float2(__uint_as_float(vv4.x), __uint_as_float(vv4.z));
            *(float2*)&Vl[r * 72 + c2] =
                make_float2(__uint_as_float(vv4.y), __uint_as_float(vv4.w));
        }
        __syncthreads();

        bool active = (kt * 64) <= (qi * 128 + wm + 15);
        if (active) {
            // ---- S = Q K^T (3-term tf32) ----
            float sacc[8][4];
#pragma unroll
            for (int nt = 0; nt < 8; nt++)
#pragma unroll
                for (int i = 0; i < 4; i++) sacc[nt][i] = 0.f;

#pragma unroll
            for (int kk = 0; kk < 64; kk += 8) {
                unsigned ah[4], al[4];
                ah[0] = __float_as_uint(Qh[(wm + g) * 68 + kk + tc]);
                ah[1] = __float_as_uint(Qh[(wm + g + 8) * 68 + kk + tc]);
                ah[2] = __float_as_uint(Qh[(wm + g) * 68 + kk + tc + 4]);
                ah[3] = __float_as_uint(Qh[(wm + g + 8) * 68 + kk + tc + 4]);
                al[0] = __float_as_uint(Ql[(wm + g) * 68 + kk + tc]);
                al[1] = __float_as_uint(Ql[(wm + g + 8) * 68 + kk + tc]);
                al[2] = __float_as_uint(Ql[(wm + g) * 68 + kk + tc + 4]);
                al[3] = __float_as_uint(Ql[(wm + g + 8) * 68 + kk + tc + 4]);
#pragma unroll
                for (int nt = 0; nt < 8; nt++) {
                    int cb = (nt * 8 + g) * 68 + kk;
                    unsigned bh[2], bl[2];
                    bh[0] = __float_as_uint(Kh[cb + tc]);
                    bh[1] = __float_as_uint(Kh[cb + tc + 4]);
                    bl[0] = __float_as_uint(Kl[cb + tc]);
                    bl[1] = __float_as_uint(Kl[cb + tc + 4]);
                    mma_tf32(sacc[nt], ah, bh);
                    mma_tf32(sacc[nt], al, bh);
                    mma_tf32(sacc[nt], ah, bl);
                }
            }

            // ---- causal mask (unscaled logits) ----
            if (kt * 64 + 63 > qi * 128 + wm) {
#pragma unroll
                for (int nt = 0; nt < 8; nt++) {
                    int col0 = kt * 64 + nt * 8 + 2 * tc;
                    if (col0     > row0) sacc[nt][0] = -1e30f;
                    if (col0 + 1 > row0) sacc[nt][1] = -1e30f;
                    if (col0     > row1) sacc[nt][2] = -1e30f;
                    if (col0 + 1 > row1) sacc[nt][3] = -1e30f;
                }
            }

            // ---- online softmax (4-lane quad owns a full row) ----
            float lm0 = -1e30f, lm1 = -1e30f;
#pragma unroll
            for (int nt = 0; nt < 8; nt++) {
                lm0 = fmaxf(lm0, fmaxf(sacc[nt][0], sacc[nt][1]));
                lm1 = fmaxf(lm1, fmaxf(sacc[nt][2], sacc[nt][3]));
            }
            lm0 = fmaxf(lm0, __shfl_xor_sync(0xffffffffu, lm0, 1));
            lm0 = fmaxf(lm0, __shfl_xor_sync(0xffffffffu, lm0, 2));
            lm1 = fmaxf(lm1, __shfl_xor_sync(0xffffffffu, lm1, 1));
            lm1 = fmaxf(lm1, __shfl_xor_sync(0xffffffffu, lm1, 2));
            float mn0 = fmaxf(m0, lm0);
            float mn1 = fmaxf(m1, lm1);
            float a0 = exp2_fast((m0 - mn0) * SC);
            float a1 = exp2_fast((m1 - mn1) * SC);
            float ps0 = 0.f, ps1 = 0.f;
#pragma unroll
            for (int nt = 0; nt < 8; nt++) {
                float p0 = exp2_fast((sacc[nt][0] - mn0) * SC);
                float p1 = exp2_fast((sacc[nt][1] - mn0) * SC);
                float p2 = exp2_fast((sacc[nt][2] - mn1) * SC);
                float p3 = exp2_fast((sacc[nt][3] - mn1) * SC);
                ps0 += p0 + p1;
                ps1 += p2 + p3;
                uint2 s0 = split1(p0), s1 = split1(p1);
                uint2 s2 = split1(p2), s3 = split1(p3);
                int cb = nt * 8 + 2 * tc;
                *(float2*)&Ph[(wm + g) * 68 + cb] =
                    make_float2(__uint_as_float(s0.x), __uint_as_float(s1.x));
                *(float2*)&Pl[(wm + g) * 68 + cb] =
                    make_float2(__uint_as_float(s0.y), __uint_as_float(s1.y));
                *(float2*)&Ph[(wm + g + 8) * 68 + cb] =
                    make_float2(__uint_as_float(s2.x), __uint_as_float(s3.x));
                *(float2*)&Pl[(wm + g + 8) * 68 + cb] =
                    make_float2(__uint_as_float(s2.y), __uint_as_float(s3.y));
            }
            ps0 += __shfl_xor_sync(0xffffffffu, ps0, 1);
            ps0 += __shfl_xor_sync(0xffffffffu, ps0, 2);
            ps1 += __shfl_xor_sync(0xffffffffu, ps1, 1);
            ps1 += __shfl_xor_sync(0xffffffffu, ps1, 2);
            l0 = l0 * a0 + ps0;
            l1 = l1 * a1 + ps1;
            m0 = mn0; m1 = mn1;
#pragma unroll
            for (int nt = 0; nt < 8; nt++) {
                o[nt][0] *= a0; o[nt][1] *= a0;
                o[nt][2] *= a1; o[nt][3] *= a1;
            }
            __syncwarp();   // own-warp P stores visible to own-warp loads

            // ---- O += P V (3-term tf32; V in natural [s][c] layout) ----
#pragma unroll
            for (int kk = 0; kk < 64; kk += 8) {
                unsigned ah[4], al[4];
                ah[0] = __float_as_uint(Ph[(wm + g) * 68 + kk + tc]);
                ah[1] = __float_as_uint(Ph[(wm + g + 8) * 68 + kk + tc]);
                ah[2] = __float_as_uint(Ph[(wm + g) * 68 + kk + tc + 4]);
                ah[3] = __float_as_uint(Ph[(wm + g + 8) * 68 + kk + tc + 4]);
                al[0] = __float_as_uint(Pl[(wm + g) * 68 + kk + tc]);
                al[1] = __float_as_uint(Pl[(wm + g + 8) * 68 + kk + tc]);
                al[2] = __float_as_uint(Pl[(wm + g) * 68 + kk + tc + 4]);
                al[3] = __float_as_uint(Pl[(wm + g + 8) * 68 + kk + tc + 4]);
#pragma unroll
                for (int nt = 0; nt < 8; nt++) {
                    int nb = nt * 8 + g;
                    unsigned bh[2], bl[2];
                    bh[0] = __float_as_uint(Vh[(kk + tc) * 72 + nb]);
                    bh[1] = __float_as_uint(Vh[(kk + tc + 4) * 72 + nb]);
                    bl[0] = __float_as_uint(Vl[(kk + tc) * 72 + nb]);
                    bl[1] = __float_as_uint(Vl[(kk + tc + 4) * 72 + nb]);
                    mma_tf32(o[nt], ah, bh);
                    mma_tf32(o[nt], al, bh);
                    mma_tf32(o[nt], ah, bl);
                }
            }
        } // active
    } // kt

    // ---- write normalized output ----
    float il0 = 1.0f / l0;
    float il1 = 1.0f / l1;
#pragma unroll
    for (int nt = 0; nt < 8; nt++) {
        int c0 = h * CH + nt * 8 + 2 * tc;
        *(float2*)&g_att[(size_t)row0 * D_MODEL + c0] =
            make_float2(o[nt][0] * il0, o[nt][1] * il0);
        *(float2*)&g_att[(size_t)row1 * D_MODEL + c0] =
            make_float2(o[nt][2] * il1, o[nt][3] * il1);
    }
}

// ---------------- launch -----------------------------------------------------
extern "C" void kernel_launch(void* const* d_in, const int* in_sizes, int n_in,
                              void* d_out, int out_size) {
    const float* x     = (const float*)d_in[0];
    const float* Wqkv  = (const float*)d_in[1];
    const float* Wproj = (const float*)d_in[2];
    float* out = (float*)d_out;

    cudaFuncSetAttribute(flash_mma2,
                         cudaFuncAttributeMaxDynamicSharedMemorySize, FLASH_SMEM);

    rope_table_kernel<<<T_SEQ, 32>>>();
    gemm_tf32<0><<<dim3(3 * D_MODEL / 128, T_SEQ / 128), 256>>>(x, Wqkv, nullptr);
    flash_mma2<<<dim3(32, NH), 256, FLASH_SMEM>>>();
    gemm_tf32<1><<<dim3(D_MODEL / 128, T_SEQ / 128), 256>>>(nullptr, Wproj, out);
}

// round 5
// speedup vs baseline: 1.2664x; 1.0013x over previous
#include <cuda_runtime.h>
#include <math.h>

#define T_SEQ  4096
#define D_MODEL 1024
#define NH      16
#define CH      64

// ---------------- scratch (device globals; no allocation allowed) ----------
__device__ uint2 g_Q2[NH * T_SEQ * CH];    // [h][t][c] tf32 {hi,lo}, rope applied
__device__ uint2 g_K2[NH * T_SEQ * CH];
__device__ uint2 g_V2[NH * T_SEQ * CH];
__device__ float g_att[T_SEQ * D_MODEL];   // [t][h*64+c]
__device__ float g_sin[T_SEQ * 32];
__device__ float g_cos[T_SEQ * 32];

// ---------------- RoPE sin/cos table ---------------------------------------
__global__ void rope_table_kernel() {
    int t = blockIdx.x;
    int p = threadIdx.x;
    double inv = pow(10000.0, -(double)(2 * p) / 64.0);
    float ang = (float)t * (float)inv;
    float s, c;
    sincosf(ang, &s, &c);
    g_sin[t * 32 + p] = s;
    g_cos[t * 32 + p] = c;
}

// ---------------- tf32 helpers ----------------------------------------------
__device__ __forceinline__ unsigned f2tf32(float x) {
    unsigned r;
    asm("cvt.rna.tf32.f32 %0, %1;" : "=r"(r) : "f"(x));
    return r;
}

__device__ __forceinline__ uint2 split1(float x) {
    unsigned h = f2tf32(x);
    unsigned l = f2tf32(x - __uint_as_float(h));
    return make_uint2(h, l);
}

__device__ __forceinline__ void mma_tf32(float* d, const unsigned* a, const unsigned* b) {
    asm volatile(
        "mma.sync.aligned.m16n8k8.row.col.f32.tf32.tf32.f32 "
        "{%0,%1,%2,%3},{%4,%5,%6,%7},{%8,%9},{%0,%1,%2,%3};"
        : "+f"(d[0]), "+f"(d[1]), "+f"(d[2]), "+f"(d[3])
        : "r"(a[0]), "r"(a[1]), "r"(a[2]), "r"(a[3]), "r"(b[0]), "r"(b[1]));
}

__device__ __forceinline__ void split4(float4 v, unsigned* hp, unsigned* lp) {
    unsigned h0 = f2tf32(v.x), h1 = f2tf32(v.y), h2 = f2tf32(v.z), h3 = f2tf32(v.w);
    *(uint4*)hp = make_uint4(h0, h1, h2, h3);
    unsigned l0 = f2tf32(v.x - __uint_as_float(h0));
    unsigned l1 = f2tf32(v.y - __uint_as_float(h1));
    unsigned l2 = f2tf32(v.z - __uint_as_float(h2));
    unsigned l3 = f2tf32(v.w - __uint_as_float(h3));
    *(uint4*)lp = make_uint4(l0, l1, l2, l3);
}

// fast exp2 on the fma pipe (arg <= 0), rel err ~2e-6
__device__ __forceinline__ float exp2_fast(float y) {
    y = fmaxf(y, -125.f);
    float n = rintf(y);
    float f = y - n;                 // [-0.5, 0.5]
    float p = 1.3333558e-3f;
    p = fmaf(p, f, 9.6181291e-3f);
    p = fmaf(p, f, 5.5504109e-2f);
    p = fmaf(p, f, 2.4022651e-1f);
    p = fmaf(p, f, 6.9314718e-1f);
    p = fmaf(p, f, 1.0f);
    return p * __int_as_float(((int)n + 127) << 23);
}

// ---------------- tf32 GEMM: C = A(row) * B(row as N x K)^T -----------------
// EPI=0: qkv (+rope, split, scatter into g_Q2/g_K2/g_V2), EPI=1: proj -> out
#define SK 20

template<int EPI>
__global__ __launch_bounds__(256) void gemm_tf32(
    const float* __restrict__ Ain, const float* __restrict__ B,
    float* __restrict__ out) {
    __shared__ unsigned Ah[128][SK], Al[128][SK], Bh[128][SK], Bl[128][SK];

    const float* A = (EPI == 1) ? g_att : Ain;

    int tid  = threadIdx.x;
    int lane = tid & 31;
    int warp = tid >> 5;
    int bm = blockIdx.y, bn = blockIdx.x;
    int warp_m = (warp >> 2) * 64;
    int warp_n = (warp & 3) * 32;
    int g  = lane >> 2;
    int tc = lane & 3;

    int r  = tid >> 2;
    int k4 = (tid & 3) * 4;
    const float* Ap0 = A + (size_t)(bm * 128 + r)      * D_MODEL + k4;
    const float* Ap1 = A + (size_t)(bm * 128 + r + 64) * D_MODEL + k4;
    const float* Bp0 = B + (size_t)(bn * 128 + r)      * D_MODEL + k4;
    const float* Bp1 = B + (size_t)(bn * 128 + r + 64) * D_MODEL + k4;

    float acc[4][4][4];
#pragma unroll
    for (int mt = 0; mt < 4; mt++)
#pragma unroll
        for (int nt = 0; nt < 4; nt++)
#pragma unroll
            for (int i = 0; i < 4; i++) acc[mt][nt][i] = 0.f;

    float4 sa0 = *(const float4*)(Ap0);
    float4 sa1 = *(const float4*)(Ap1);
    float4 sb0 = *(const float4*)(Bp0);
    float4 sb1 = *(const float4*)(Bp1);

    for (int k0 = 0; k0 < D_MODEL; k0 += 16) {
        __syncthreads();
        split4(sa0, &Ah[r][k4],      &Al[r][k4]);
        split4(sa1, &Ah[r + 64][k4], &Al[r + 64][k4]);
        split4(sb0, &Bh[r][k4],      &Bl[r][k4]);
        split4(sb1, &Bh[r + 64][k4], &Bl[r + 64][k4]);
        __syncthreads();
        if (k0 + 16 < D_MODEL) {
            sa0 = *(const float4*)(Ap0 + k0 + 16);
            sa1 = *(const float4*)(Ap1 + k0 + 16);
            sb0 = *(const float4*)(Bp0 + k0 + 16);
            sb1 = *(const float4*)(Bp1 + k0 + 16);
        }
#pragma unroll
        for (int kk = 0; kk < 16; kk += 8) {
            unsigned afh[4][4], afl[4][4], bfh[4][2], bfl[4][2];
#pragma unroll
            for (int mt = 0; mt < 4; mt++) {
                int row = warp_m + mt * 16 + g;
                afh[mt][0] = Ah[row][kk + tc];
                afh[mt][1] = Ah[row + 8][kk + tc];
                afh[mt][2] = Ah[row][kk + tc + 4];
                afh[mt][3] = Ah[row + 8][kk + tc + 4];
                afl[mt][0] = Al[row][kk + tc];
                afl[mt][1] = Al[row + 8][kk + tc];
                afl[mt][2] = Al[row][kk + tc + 4];
                afl[mt][3] = Al[row + 8][kk + tc + 4];
            }
#pragma unroll
            for (int nt = 0; nt < 4; nt++) {
                int col = warp_n + nt * 8 + g;
                bfh[nt][0] = Bh[col][kk + tc];
                bfh[nt][1] = Bh[col][kk + tc + 4];
                bfl[nt][0] = Bl[col][kk + tc];
                bfl[nt][1] = Bl[col][kk + tc + 4];
            }
#pragma unroll
            for (int mt = 0; mt < 4; mt++)
#pragma unroll
                for (int nt = 0; nt < 4; nt++) {
                    mma_tf32(acc[mt][nt], afh[mt], bfh[nt]);
                    mma_tf32(acc[mt][nt], afh[mt], bfl[nt]);
                    mma_tf32(acc[mt][nt], afl[mt], bfh[nt]);
                }
        }
    }

    // ---- epilogue ----
    if (EPI == 0) {
        int mat = (bn * 128) >> 10;                 // 0=q,1=k,2=v
        uint2* dst = (mat == 0) ? g_Q2 : (mat == 1 ? g_K2 : g_V2);
#pragma unroll
        for (int mt = 0; mt < 4; mt++)
#pragma unroll
            for (int nt = 0; nt < 4; nt++) {
                int colb = bn * 128 + warp_n + nt * 8 + 2 * tc;
                int cm = colb & 1023;
                int h = cm >> 6, cc = cm & 63, p = cc >> 1;
#pragma unroll
                for (int half = 0; half < 2; half++) {
                    int row = bm * 128 + warp_m + mt * 16 + g + half * 8;
                    float e = acc[mt][nt][half * 2 + 0];
                    float o = acc[mt][nt][half * 2 + 1];
                    if (mat != 2) {
                        float sn = g_sin[row * 32 + p];
                        float cs = g_cos[row * 32 + p];
                        float e2 = e * cs - o * sn;
                        o = o * cs + e * sn;
                        e = e2;
                    }
                    size_t idx = ((size_t)h * T_SEQ + row) * CH + cc;
                    uint2 es = split1(e), os = split1(o);
                    *(uint4*)&dst[idx] = make_uint4(es.x, es.y, os.x, os.y);
                }
            }
    } else {
#pragma unroll
        for (int mt = 0; mt < 4; mt++)
#pragma unroll
            for (int nt = 0; nt < 4; nt++) {
                int colb = bn * 128 + warp_n + nt * 8 + 2 * tc;
#pragma unroll
                for (int half = 0; half < 2; half++) {
                    int row = bm * 128 + warp_m + mt * 16 + g + half * 8;
                    *(float2*)&out[(size_t)row * D_MODEL + colb] =
                        make_float2(acc[mt][nt][half * 2 + 0],
                                    acc[mt][nt][half * 2 + 1]);
                }
            }
    }
}

// ---------------- tensor-core flash attention v2 -----------------------------
// BM=128 x BN=64; 8 warps, each owns 16 full rows (no cross-warp softmax).
// smem float arrays: Q/K/P stride 68 (conflict-free A/B frag LDS), V stride 72.
#define QH_OFF 0
#define QL_OFF 8704
#define KH_OFF 17408
#define KL_OFF 21760
#define VH_OFF 26112
#define VL_OFF 30720
#define PH_OFF 35328
#define PL_OFF 44032
#define FLASH_SMEM (52736 * 4)

__global__ __launch_bounds__(256) void flash_mma2() {
    extern __shared__ float sf[];
    float* Qh = sf + QH_OFF;  float* Ql = sf + QL_OFF;
    float* Kh = sf + KH_OFF;  float* Kl = sf + KL_OFF;
    float* Vh = sf + VH_OFF;  float* Vl = sf + VL_OFF;
    float* Ph = sf + PH_OFF;  float* Pl = sf + PL_OFF;

    int h  = blockIdx.y;
    int qi = 31 - blockIdx.x;                 // heavy tiles first
    int tid = threadIdx.x;
    int lane = tid & 31;
    int warp = tid >> 5;
    int g  = lane >> 2;
    int tc = lane & 3;
    int wm = warp * 16;

    size_t hbase = (size_t)h * T_SEQ * CH;

    // load Q tile: 128 rows x 64 cols of {hi,lo}
#pragma unroll
    for (int t = 0; t < 16; t++) {
        int i = tid + t * 256;
        int r = i >> 5, c2 = (i & 31) * 2;
        uint4 q = *(const uint4*)&g_Q2[hbase + (size_t)(qi * 128 + r) * CH + c2];
        *(float2*)&Qh[r * 68 + c2] =
            make_float2(__uint_as_float(q.x), __uint_as_float(q.z));
        *(float2*)&Ql[r * 68 + c2] =
            make_float2(__uint_as_float(q.y), __uint_as_float(q.w));
    }

    float m0 = -1e30f, m1 = -1e30f, l0 = 0.f, l1 = 0.f;
    float o[8][4];
#pragma unroll
    for (int nt = 0; nt < 8; nt++)
#pragma unroll
        for (int i = 0; i < 4; i++) o[nt][i] = 0.f;

    const float SC = 0.125f * 1.44269504f;     // scale * log2(e)
    int row0 = qi * 128 + wm + g;
    int row1 = row0 + 8;
    int ktmax = 2 * qi + 1;

    for (int kt = 0; kt <= ktmax; kt++) {
        __syncthreads();   // all warps done reading prev K/V
#pragma unroll
        for (int t = 0; t < 8; t++) {
            int i = tid + t * 256;
            int r = i >> 5, c2 = (i & 31) * 2;
            size_t gi = hbase + (size_t)(kt * 64 + r) * CH + c2;
            uint4 kk4 = *(const uint4*)&g_K2[gi];
            *(float2*)&Kh[r * 68 + c2] =
                make_float2(__uint_as_float(kk4.x), __uint_as_float(kk4.z));
            *(float2*)&Kl[r * 68 + c2] =
                make_float2(__uint_as_float(kk4.y), __uint_as_float(kk4.w));
            uint4 vv4 = *(const uint4*)&g_V2[gi];
            *(float2*)&Vh[r * 72 + c2] =
                make_float2(__uint_as_float(vv4.x), __uint_as_float(vv4.z));
            *(float2*)&Vl[r * 72 + c2] =
                make_float2(__uint_as_float(vv4.y), __uint_as_float(vv4.w));
        }
        __syncthreads();

        bool active = (kt * 64) <= (qi * 128 + wm + 15);
        if (active) {
            // ---- S = Q K^T (3-term tf32) ----
            float sacc[8][4];
#pragma unroll
            for (int nt = 0; nt < 8; nt++)
#pragma unroll
                for (int i = 0; i < 4; i++) sacc[nt][i] = 0.f;

#pragma unroll
            for (int kk = 0; kk < 64; kk += 8) {
                unsigned ah[4], al[4];
                ah[0] = __float_as_uint(Qh[(wm + g) * 68 + kk + tc]);
                ah[1] = __float_as_uint(Qh[(wm + g + 8) * 68 + kk + tc]);
                ah[2] = __float_as_uint(Qh[(wm + g) * 68 + kk + tc + 4]);
                ah[3] = __float_as_uint(Qh[(wm + g + 8) * 68 + kk + tc + 4]);
                al[0] = __float_as_uint(Ql[(wm + g) * 68 + kk + tc]);
                al[1] = __float_as_uint(Ql[(wm + g + 8) * 68 + kk + tc]);
                al[2] = __float_as_uint(Ql[(wm + g) * 68 + kk + tc + 4]);
                al[3] = __float_as_uint(Ql[(wm + g + 8) * 68 + kk + tc + 4]);
#pragma unroll
                for (int nt = 0; nt < 8; nt++) {
                    int cb = (nt * 8 + g) * 68 + kk;
                    unsigned bh[2], bl[2];
                    bh[0] = __float_as_uint(Kh[cb + tc]);
                    bh[1] = __float_as_uint(Kh[cb + tc + 4]);
                    bl[0] = __float_as_uint(Kl[cb + tc]);
                    bl[1] = __float_as_uint(Kl[cb + tc + 4]);
                    mma_tf32(sacc[nt], ah, bh);
                    mma_tf32(sacc[nt], al, bh);
                    mma_tf32(sacc[nt], ah, bl);
                }
            }

            // ---- causal mask (unscaled logits) ----
            if (kt * 64 + 63 > qi * 128 + wm) {
#pragma unroll
                for (int nt = 0; nt < 8; nt++) {
                    int col0 = kt * 64 + nt * 8 + 2 * tc;
                    if (col0     > row0) sacc[nt][0] = -1e30f;
                    if (col0 + 1 > row0) sacc[nt][1] = -1e30f;
                    if (col0     > row1) sacc[nt][2] = -1e30f;
                    if (col0 + 1 > row1) sacc[nt][3] = -1e30f;
                }
            }

            // ---- online softmax (4-lane quad owns a full row) ----
            float lm0 = -1e30f, lm1 = -1e30f;
#pragma unroll
            for (int nt = 0; nt < 8; nt++) {
                lm0 = fmaxf(lm0, fmaxf(sacc[nt][0], sacc[nt][1]));
                lm1 = fmaxf(lm1, fmaxf(sacc[nt][2], sacc[nt][3]));
            }
            lm0 = fmaxf(lm0, __shfl_xor_sync(0xffffffffu, lm0, 1));
            lm0 = fmaxf(lm0, __shfl_xor_sync(0xffffffffu, lm0, 2));
            lm1 = fmaxf(lm1, __shfl_xor_sync(0xffffffffu, lm1, 1));
            lm1 = fmaxf(lm1, __shfl_xor_sync(0xffffffffu, lm1, 2));
            float mn0 = fmaxf(m0, lm0);
            float mn1 = fmaxf(m1, lm1);
            float a0 = exp2_fast((m0 - mn0) * SC);
            float a1 = exp2_fast((m1 - mn1) * SC);
            float ps0 = 0.f, ps1 = 0.f;
#pragma unroll
            for (int nt = 0; nt < 8; nt++) {
                float p0 = exp2_fast((sacc[nt][0] - mn0) * SC);
                float p1 = exp2_fast((sacc[nt][1] - mn0) * SC);
                float p2 = exp2_fast((sacc[nt][2] - mn1) * SC);
                float p3 = exp2_fast((sacc[nt][3] - mn1) * SC);
                ps0 += p0 + p1;
                ps1 += p2 + p3;
                uint2 s0 = split1(p0), s1 = split1(p1);
                uint2 s2 = split1(p2), s3 = split1(p3);
                int cb = nt * 8 + 2 * tc;
                *(float2*)&Ph[(wm + g) * 68 + cb] =
                    make_float2(__uint_as_float(s0.x), __uint_as_float(s1.x));
                *(float2*)&Pl[(wm + g) * 68 + cb] =
                    make_float2(__uint_as_float(s0.y), __uint_as_float(s1.y));
                *(float2*)&Ph[(wm + g + 8) * 68 + cb] =
                    make_float2(__uint_as_float(s2.x), __uint_as_float(s3.x));
                *(float2*)&Pl[(wm + g + 8) * 68 + cb] =
                    make_float2(__uint_as_float(s2.y), __uint_as_float(s3.y));
            }
            ps0 += __shfl_xor_sync(0xffffffffu, ps0, 1);
            ps0 += __shfl_xor_sync(0xffffffffu, ps0, 2);
            ps1 += __shfl_xor_sync(0xffffffffu, ps1, 1);
            ps1 += __shfl_xor_sync(0xffffffffu, ps1, 2);
            l0 = l0 * a0 + ps0;
            l1 = l1 * a1 + ps1;
            m0 = mn0; m1 = mn1;
#pragma unroll
            for (int nt = 0; nt < 8; nt++) {
                o[nt][0] *= a0; o[nt][1] *= a0;
                o[nt][2] *= a1; o[nt][3] *= a1;
            }
            __syncwarp();   // own-warp P stores visible to own-warp loads

            // ---- O += P V (3-term tf32; V in natural [s][c] layout) ----
#pragma unroll
            for (int kk = 0; kk < 64; kk += 8) {
                unsigned ah[4], al[4];
                ah[0] = __float_as_uint(Ph[(wm + g) * 68 + kk + tc]);
                ah[1] = __float_as_uint(Ph[(wm + g + 8) * 68 + kk + tc]);
                ah[2] = __float_as_uint(Ph[(wm + g) * 68 + kk + tc + 4]);
                ah[3] = __float_as_uint(Ph[(wm + g + 8) * 68 + kk + tc + 4]);
                al[0] = __float_as_uint(Pl[(wm + g) * 68 + kk + tc]);
                al[1] = __float_as_uint(Pl[(wm + g + 8) * 68 + kk + tc]);
                al[2] = __float_as_uint(Pl[(wm + g) * 68 + kk + tc + 4]);
                al[3] = __float_as_uint(Pl[(wm + g + 8) * 68 + kk + tc + 4]);
#pragma unroll
                for (int nt = 0; nt < 8; nt++) {
                    int nb = nt * 8 + g;
                    unsigned bh[2], bl[2];
                    bh[0] = __float_as_uint(Vh[(kk + tc) * 72 + nb]);
                    bh[1] = __float_as_uint(Vh[(kk + tc + 4) * 72 + nb]);
                    bl[0] = __float_as_uint(Vl[(kk + tc) * 72 + nb]);
                    bl[1] = __float_as_uint(Vl[(kk + tc + 4) * 72 + nb]);
                    mma_tf32(o[nt], ah, bh);
                    mma_tf32(o[nt], al, bh);
                    mma_tf32(o[nt], ah, bl);
                }
            }
        } // active
    } // kt

    // ---- write normalized output ----
    float il0 = 1.0f / l0;
    float il1 = 1.0f / l1;
#pragma unroll
    for (int nt = 0; nt < 8; nt++) {
        int c0 = h * CH + nt * 8 + 2 * tc;
        *(float2*)&g_att[(size_t)row0 * D_MODEL + c0] =
            make_float2(o[nt][0] * il0, o[nt][1] * il0);
        *(float2*)&g_att[(size_t)row1 * D_MODEL + c0] =
            make_float2(o[nt][2] * il1, o[nt][3] * il1);
    }
}

// ---------------- launch -----------------------------------------------------
extern "C" void kernel_launch(void* const* d_in, const int* in_sizes, int n_in,
                              void* d_out, int out_size) {
    const float* x     = (const float*)d_in[0];
    const float* Wqkv  = (const float*)d_in[1];
    const float* Wproj = (const float*)d_in[2];
    float* out = (float*)d_out;

    cudaFuncSetAttribute(flash_mma2,
                         cudaFuncAttributeMaxDynamicSharedMemorySize, FLASH_SMEM);

    rope_table_kernel<<<T_SEQ, 32>>>();
    gemm_tf32<0><<<dim3(3 * D_MODEL / 128, T_SEQ / 128), 256>>>(x, Wqkv, nullptr);
    flash_mma2<<<dim3(32, NH), 256, FLASH_SMEM>>>();
    gemm_tf32<1><<<dim3(D_MODEL / 128, T_SEQ / 128), 256>>>(nullptr, Wproj, out);
}